// round 2
// baseline (speedup 1.0000x reference)
#include <cuda_runtime.h>

// QuantumConv closed form.
//
// The reference circuit measures only P(qubit0 = 1). All parametric rotations
// on qubits 1..8 commute with the measurement projector |1><1|_0 (x) I and drop
// out; RZ on qubit 0 is diagonal and drops out; the CZ ring reduces to a
// conditional Z1*Z8 whose product-state expectation is cos(f1)*cos(f8).
// Exact result:
//   p1 = 0.5 * ( 1 - cos(pi*t0)*cos(pi*t1)*cos(f0)
//                  + sin(pi*t0)*cos(pi*t1)*sin(f0)*cos(f1)*cos(f8) )
// with f0 = in[b,y,x], f1 = in[b,y,x+1], f8 = in[b,y+2,x+2].

#define BATCH 16
#define HH 28
#define WW 28
#define NOUT 26
#define NP (BATCH * NOUT * NOUT)   // 10816

__global__ void qconv_closed_form(const float* __restrict__ in,
                                  const float* __restrict__ theta,
                                  float* __restrict__ out) {
    int idx = blockIdx.x * blockDim.x + threadIdx.x;
    if (idx >= NP) return;

    int x = idx % NOUT;
    int t = idx / NOUT;
    int y = t % NOUT;
    int b = t / NOUT;

    const float* base = in + (b * HH + y) * WW + x;
    float f0 = base[0];
    float f1 = base[1];
    float f8 = base[2 * WW + 2];

    const float PI = 3.14159265358979323846f;
    float a0 = PI * theta[0];
    float a1 = PI * theta[1];
    float sa, ca;
    sincosf(a0, &sa, &ca);
    float cb = cosf(a1);
    float K1 = ca * cb;   // cos(pi t0) cos(pi t1)
    float K2 = sa * cb;   // sin(pi t0) cos(pi t1)

    float s0, c0;
    sincosf(f0, &s0, &c0);
    float r = 0.5f * (1.0f - K1 * c0 + K2 * s0 * cosf(f1) * cosf(f8));
    out[idx] = r;
}

extern "C" void kernel_launch(void* const* d_in, const int* in_sizes, int n_in,
                              void* d_out, int out_size) {
    const float* input = (const float*)d_in[0];   // (16,28,28) float32
    const float* theta = (const float*)d_in[1];   // (1,27) float32
    float* out = (float*)d_out;                   // (16,26,26) float32

    (void)in_sizes; (void)n_in; (void)out_size;

    int threads = 256;
    int blocks = (NP + threads - 1) / threads;    // 43
    qconv_closed_form<<<blocks, threads>>>(input, theta, out);
}

// round 3
// speedup vs baseline: 1.3819x; 1.3819x over previous
#include <cuda_runtime.h>

// QuantumConv closed form (see R1 derivation):
//   p1 = 0.5 * ( 1 - cos(pi*t0)*cos(pi*t1)*cos(f0)
//                  + sin(pi*t0)*cos(pi*t1)*sin(f0)*cos(f1)*cos(f8) )
// with f0 = in[b,y,x], f1 = in[b,y,x+1], f8 = in[b,y+2,x+2].
//
// R3 change: MUFU fast-trig intrinsics instead of libm range-reduced
// sincosf/cosf. Valid because f in [0,1) and pi*theta in [-pi^2/2, pi^2/2],
// both far inside the MUFU-accurate range; abs err ~1e-6 << 1e-3 gate.
// All 5 global loads issued before any dependent math (MLP=5).

#define BATCH 16
#define HH 28
#define WW 28
#define NOUT 26
#define NP (BATCH * NOUT * NOUT)   // 10816

__global__ __launch_bounds__(128, 1)
void qconv_closed_form(const float* __restrict__ in,
                       const float* __restrict__ theta,
                       float* __restrict__ out) {
    int idx = blockIdx.x * blockDim.x + threadIdx.x;
    if (idx >= NP) return;

    int t = idx / NOUT;          // const-div -> mulhi
    int x = idx - t * NOUT;
    int b = t / NOUT;
    int y = t - b * NOUT;

    const float* base = in + (b * HH + y) * WW + x;

    // Issue all loads up front so their latencies overlap.
    float f0 = __ldg(base);
    float f1 = __ldg(base + 1);
    float f8 = __ldg(base + 2 * WW + 2);
    float t0 = __ldg(theta);
    float t1 = __ldg(theta + 1);

    const float PI = 3.14159265358979323846f;
    float a0 = PI * t0;
    float a1 = PI * t1;

    // MUFU fast trig (no range reduction needed for these argument ranges).
    float sa, ca;
    __sincosf(a0, &sa, &ca);
    float cb = __cosf(a1);
    float K1 = ca * cb;          // cos(pi t0) cos(pi t1)
    float K2 = sa * cb;          // sin(pi t0) cos(pi t1)

    float s0, c0;
    __sincosf(f0, &s0, &c0);
    float c1 = __cosf(f1);
    float c8 = __cosf(f8);

    out[idx] = 0.5f * (1.0f - K1 * c0 + K2 * s0 * c1 * c8);
}

extern "C" void kernel_launch(void* const* d_in, const int* in_sizes, int n_in,
                              void* d_out, int out_size) {
    const float* input = (const float*)d_in[0];   // (16,28,28) float32
    const float* theta = (const float*)d_in[1];   // (1,27) float32
    float* out = (float*)d_out;                   // (16,26,26) float32

    (void)in_sizes; (void)n_in; (void)out_size;

    int threads = 128;
    int blocks = (NP + threads - 1) / threads;    // 85 blocks, single wave
    qconv_closed_form<<<blocks, threads>>>(input, theta, out);
}